// round 13
// baseline (speedup 1.0000x reference)
#include <cuda_runtime.h>
#include <cuda_bf16.h>
#include <math.h>
#include <stdint.h>

// Problem constants
#define B_  32
#define N_  4096
#define C_  512
#define EPS_INV 10.0f          // 1/EPS_SINKHORN

#define CHUNKS 32              // chunk-blocks per batch -> grid 1024
#define ROWS_PER_BLOCK (N_ / CHUNKS)   // 128
#define THREADS1 128           // 4 warps -> 8 blocks/SM resident, whole grid in ONE wave
#define NWARPS (THREADS1 / 32)

// Scratch (allocation-free rule: __device__ globals)
__device__ float        g_vec[B_ * CHUNKS * C_];   // partial weighted sums: 2 MB
__device__ float        g_E[B_ * CHUNKS];          // partial exp-sums
__device__ unsigned int g_cnt[B_];                 // zero-init; last block resets -> replayable

// ---------------------------------------------------------------------------
// Fused single-pass kernel, small-CTA edition. Grid = 1024 blocks of 128
// threads, all co-resident (148 SMs x 8 blocks capacity): per-SM work
// imbalance drops from 15.6% (grid 512, 4/3 blocks per SM) to 1.2% (7/6.92).
// Register prefetch pipelines the next row's LDG.128 under the current row's
// reduce/exp chain. Last chunk-block per batch does the cross-chunk combine.
//
// Per row: e = exp(10*(cos_sim - 1)) (shift m=0 valid since cos_sim <= 1),
// accumulate (e/|v|)*v and e. Softmax Z folds out analytically:
//   obs = num / (E + 1e-6*S),  total_mass = E / S,  S = E + exp(-10*dustbin).
// ---------------------------------------------------------------------------
__global__ __launch_bounds__(THREADS1, 8)
void uot_fused(const float* __restrict__ prompt,
               const float* __restrict__ vfeats,
               const float* __restrict__ dustbin_param,
               float* __restrict__ out)
{
    const int b     = blockIdx.x / CHUNKS;
    const int chunk = blockIdx.x % CHUNKS;
    const int tid   = threadIdx.x;
    const int wid   = tid >> 5;
    const int lane  = tid & 31;

    __shared__ float sacc[NWARPS][C_];       // 8KB
    __shared__ float sEw[NWARPS];
    __shared__ float sEtot;
    __shared__ int   sLast;

    // ---- Prompt into registers + its norm (warp-local; C_=512=4*128) ----
    float4 p[4];
    {
        const float4* pr = (const float4*)(prompt + (size_t)b * C_);
        float ss = 0.f;
        #pragma unroll
        for (int j = 0; j < 4; j++) {
            p[j] = __ldg(pr + j * 32 + lane);
            ss += p[j].x * p[j].x + p[j].y * p[j].y + p[j].z * p[j].z + p[j].w * p[j].w;
        }
        #pragma unroll
        for (int o = 16; o; o >>= 1) ss += __shfl_xor_sync(0xffffffffu, ss, o);
        float pinv = rsqrtf(fmaxf(ss, 1e-24f));
        #pragma unroll
        for (int j = 0; j < 4; j++) {        // pre-scale prompt by 1/|p|
            p[j].x *= pinv; p[j].y *= pinv; p[j].z *= pinv; p[j].w *= pinv;
        }
    }

    // ---- Main streaming loop: register-prefetch pipeline, 1 row/warp/iter ----
    float acc[16];
    #pragma unroll
    for (int i = 0; i < 16; i++) acc[i] = 0.f;
    float Eacc = 0.f;

    const float* base = vfeats + ((size_t)b * N_ + (size_t)chunk * ROWS_PER_BLOCK) * C_;

    float4 v[4];
    {
        const float4* row0 = (const float4*)(base + (size_t)wid * C_);
        #pragma unroll
        for (int j = 0; j < 4; j++) v[j] = __ldcs(row0 + j * 32 + lane);
    }

    for (int r = wid; r < ROWS_PER_BLOCK; r += NWARPS) {
        // Snapshot current row, immediately issue next row's loads
        float4 c[4];
        #pragma unroll
        for (int j = 0; j < 4; j++) c[j] = v[j];

        const int rn = r + NWARPS;
        if (rn < ROWS_PER_BLOCK) {
            const float4* rown = (const float4*)(base + (size_t)rn * C_);
            #pragma unroll
            for (int j = 0; j < 4; j++) v[j] = __ldcs(rown + j * 32 + lane);
        }

        float dpv = 0.f, dvv = 0.f;
        #pragma unroll
        for (int j = 0; j < 4; j++) {
            dpv += c[j].x * p[j].x + c[j].y * p[j].y + c[j].z * p[j].z + c[j].w * p[j].w;
            dvv += c[j].x * c[j].x + c[j].y * c[j].y + c[j].z * c[j].z + c[j].w * c[j].w;
        }
        #pragma unroll
        for (int o = 16; o; o >>= 1) {       // interleaved butterflies overlap
            dpv += __shfl_xor_sync(0xffffffffu, dpv, o);
            dvv += __shfl_xor_sync(0xffffffffu, dvv, o);
        }
        float invn = rsqrtf(fmaxf(dvv, 1e-24f));
        float e    = __expf(EPS_INV * (dpv * invn - 1.0f));   // p already unit-norm
        float w    = e * invn;               // weight applied to the RAW row
        Eacc += e;
        #pragma unroll
        for (int j = 0; j < 4; j++) {
            acc[j * 4 + 0] += w * c[j].x;
            acc[j * 4 + 1] += w * c[j].y;
            acc[j * 4 + 2] += w * c[j].z;
            acc[j * 4 + 3] += w * c[j].w;
        }
    }

    // ---- Cross-warp combine in smem ----
    float4* sa4 = (float4*)sacc[wid];
    #pragma unroll
    for (int j = 0; j < 4; j++)
        sa4[j * 32 + lane] = make_float4(acc[j*4+0], acc[j*4+1], acc[j*4+2], acc[j*4+3]);
    if (lane == 0) sEw[wid] = Eacc;
    __syncthreads();

    const int slot = b * CHUNKS + chunk;
    #pragma unroll
    for (int c = tid; c < C_; c += THREADS1) {
        float s = 0.f;
        #pragma unroll
        for (int w = 0; w < NWARPS; w++) s += sacc[w][c];
        g_vec[slot * C_ + c] = s;
    }
    if (tid == 0) {
        float s = 0.f;
        #pragma unroll
        for (int w = 0; w < NWARPS; w++) s += sEw[w];
        g_E[slot] = s;
    }

    // ---- Last-block-per-batch does the final combine ----
    __syncthreads();
    if (tid == 0) {
        __threadfence();                     // release partials
        unsigned int old = atomicAdd(&g_cnt[b], 1u);
        sLast = (old == CHUNKS - 1);
    }
    __syncthreads();
    if (!sLast) return;
    __threadfence();                         // acquire others' partials

    if (tid < 32) {                          // CHUNKS == 32
        float e = g_E[b * CHUNKS + tid];
        #pragma unroll
        for (int o = 16; o; o >>= 1)
            e += __shfl_xor_sync(0xffffffffu, e, o);
        if (tid == 0) sEtot = e;
    }
    __syncthreads();

    const float E    = sEtot;
    const float ebin = __expf(-EPS_INV * dustbin_param[0]);
    const float S    = E + ebin;
    const float dinv = 1.0f / (E + 1e-6f * S);

    #pragma unroll
    for (int c = tid; c < C_; c += THREADS1) {
        float num = 0.f;
        #pragma unroll
        for (int ch = 0; ch < CHUNKS; ch++)
            num += g_vec[(b * CHUNKS + ch) * C_ + c];
        out[b * C_ + c] = num * dinv;
    }
    if (tid == 0) {
        out[B_ * C_ + b] = E / S;            // total_mass
        g_cnt[b] = 0;                        // reset for next graph replay
    }
}

// ---------------------------------------------------------------------------
extern "C" void kernel_launch(void* const* d_in, const int* in_sizes, int n_in,
                              void* d_out, int out_size)
{
    const float* prompt  = (const float*)d_in[0];   // (32,1,512)
    const float* vfeats  = (const float*)d_in[1];   // (32,4096,512)
    // d_in[2] = dustbin_token : unused by the reference computation
    const float* dparam  = (const float*)d_in[3];   // (1,)
    float* out = (float*)d_out;

    uot_fused<<<B_ * CHUNKS, THREADS1>>>(prompt, vfeats, dparam, out);
}

// round 14
// speedup vs baseline: 1.3033x; 1.3033x over previous
#include <cuda_runtime.h>
#include <cuda_bf16.h>
#include <math.h>
#include <stdint.h>

// Problem constants
#define B_  32
#define N_  4096
#define C_  512
#define EPS_INV 10.0f          // 1/EPS_SINKHORN

#define THREADS1 256           // 8 warps
#define NWARPS (THREADS1 / 32)
#define BLOCKS_PER_B 18        // blocks per batch -> grid 576 = 18*32 (<= 592 slots, ONE wave)
#define WARPS_PER_B (BLOCKS_PER_B * NWARPS)   // 144 warps share one batch's 4096 rows

// Per-batch accumulators (allocation-free rule: __device__ globals; zero-init
// at module load, re-zeroed by the finishing block for graph replay)
__device__ float        g_vec[B_ * C_];     // 64KB: REDG-accumulated weighted sums
__device__ float        g_E[B_];            // REDG-accumulated exp-sums
__device__ unsigned int g_cnt[B_];          // last-arrival counters

// ---------------------------------------------------------------------------
// Fused single-pass kernel, warp-interleaved balanced edition.
// grid = 576 blocks of 256 threads: 18 blocks per batch, all co-resident.
// Warp k (of a batch's 144) processes rows k, k+144, k+288, ... -> every warp
// in the grid gets 28 or 29 rows (+2% max imbalance, vs +15.6% for the old
// chunked grid-512 layout whose 4-vs-3 blocks/SM placement capped DRAM at 70%).
// Per-warp partials live in registers across all rows; one REDG flush per
// block; the 18th block of each batch finalizes that batch's output.
//
// Per row: e = exp(10*(cos_sim - 1)) (shift m=0 valid since cos_sim <= 1),
// accumulate (e/|v|)*v and e. Softmax Z folds out analytically:
//   obs = num / (E + 1e-6*S),  total_mass = E / S,  S = E + exp(-10*dustbin).
// ---------------------------------------------------------------------------
__global__ __launch_bounds__(THREADS1, 4)
void uot_fused(const float* __restrict__ prompt,
               const float* __restrict__ vfeats,
               const float* __restrict__ dustbin_param,
               float* __restrict__ out)
{
    const int b    = blockIdx.x / BLOCKS_PER_B;
    const int jblk = blockIdx.x % BLOCKS_PER_B;
    const int tid  = threadIdx.x;
    const int wid  = tid >> 5;
    const int lane = tid & 31;
    const int wb   = jblk * NWARPS + wid;    // warp index within batch: 0..143

    __shared__ float sacc[NWARPS][C_];       // 16KB
    __shared__ float sEw[NWARPS];
    __shared__ int   sLast;

    // ---- Prompt into registers + its norm (warp-local) ----
    float4 p[4];
    {
        const float4* pr = (const float4*)(prompt + (size_t)b * C_);
        float ss = 0.f;
        #pragma unroll
        for (int j = 0; j < 4; j++) {
            p[j] = __ldg(pr + j * 32 + lane);
            ss += p[j].x * p[j].x + p[j].y * p[j].y + p[j].z * p[j].z + p[j].w * p[j].w;
        }
        #pragma unroll
        for (int o = 16; o; o >>= 1) ss += __shfl_xor_sync(0xffffffffu, ss, o);
        float pinv = rsqrtf(fmaxf(ss, 1e-24f));
        #pragma unroll
        for (int j = 0; j < 4; j++) {        // pre-scale prompt by 1/|p|
            p[j].x *= pinv; p[j].y *= pinv; p[j].z *= pinv; p[j].w *= pinv;
        }
    }

    // ---- Main streaming loop: rows wb, wb+144, wb+288, ... ----
    float acc[16];
    #pragma unroll
    for (int i = 0; i < 16; i++) acc[i] = 0.f;
    float Eacc = 0.f;

    const float* vb = vfeats + (size_t)b * N_ * C_;

    for (int r = wb; r < N_; r += WARPS_PER_B) {
        const float4* row = (const float4*)(vb + (size_t)r * C_);
        float4 v[4];
        float dpv = 0.f, dvv = 0.f;
        #pragma unroll
        for (int j = 0; j < 4; j++)
            v[j] = __ldcs(row + j * 32 + lane);
        #pragma unroll
        for (int j = 0; j < 4; j++) {
            dpv += v[j].x * p[j].x + v[j].y * p[j].y + v[j].z * p[j].z + v[j].w * p[j].w;
            dvv += v[j].x * v[j].x + v[j].y * v[j].y + v[j].z * v[j].z + v[j].w * v[j].w;
        }
        #pragma unroll
        for (int o = 16; o; o >>= 1) {       // interleaved butterflies overlap
            dpv += __shfl_xor_sync(0xffffffffu, dpv, o);
            dvv += __shfl_xor_sync(0xffffffffu, dvv, o);
        }
        float invn = rsqrtf(fmaxf(dvv, 1e-24f));
        float e    = __expf(EPS_INV * (dpv * invn - 1.0f));   // p already unit-norm
        float w    = e * invn;               // weight applied to the RAW row
        Eacc += e;
        #pragma unroll
        for (int j = 0; j < 4; j++) {
            acc[j * 4 + 0] += w * v[j].x;
            acc[j * 4 + 1] += w * v[j].y;
            acc[j * 4 + 2] += w * v[j].z;
            acc[j * 4 + 3] += w * v[j].w;
        }
    }

    // ---- Cross-warp combine in smem, then one REDG flush per block ----
    float4* sa4 = (float4*)sacc[wid];
    #pragma unroll
    for (int j = 0; j < 4; j++)
        sa4[j * 32 + lane] = make_float4(acc[j*4+0], acc[j*4+1], acc[j*4+2], acc[j*4+3]);
    if (lane == 0) sEw[wid] = Eacc;
    __syncthreads();

    #pragma unroll
    for (int c = tid; c < C_; c += THREADS1) {   // 2 iterations
        float s = 0.f;
        #pragma unroll
        for (int w = 0; w < NWARPS; w++) s += sacc[w][c];
        atomicAdd(&g_vec[b * C_ + c], s);        // no return use -> REDG
    }
    if (tid == 0) {
        float s = 0.f;
        #pragma unroll
        for (int w = 0; w < NWARPS; w++) s += sEw[w];
        atomicAdd(&g_E[b], s);
    }

    // ---- Last-of-18 block per batch finalizes ----
    __threadfence();                         // release REDs
    __syncthreads();
    if (tid == 0) {
        unsigned int old = atomicAdd(&g_cnt[b], 1u);
        sLast = (old == BLOCKS_PER_B - 1);
    }
    __syncthreads();
    if (!sLast) return;
    __threadfence();                         // acquire others' REDs

    const float E    = g_E[b];               // no prior LDG of g_vec/g_E in this block: L1 clean
    const float ebin = __expf(-EPS_INV * dustbin_param[0]);
    const float S    = E + ebin;
    const float dinv = 1.0f / (E + 1e-6f * S);

    #pragma unroll
    for (int c = tid; c < C_; c += THREADS1) {
        float num = g_vec[b * C_ + c];
        out[b * C_ + c] = num * dinv;
        g_vec[b * C_ + c] = 0.f;             // re-arm for next graph replay
    }
    if (tid == 0) {
        out[B_ * C_ + b] = E / S;            // total_mass
        g_E[b] = 0.f;
        g_cnt[b] = 0u;
    }
}

// ---------------------------------------------------------------------------
extern "C" void kernel_launch(void* const* d_in, const int* in_sizes, int n_in,
                              void* d_out, int out_size)
{
    const float* prompt  = (const float*)d_in[0];   // (32,1,512)
    const float* vfeats  = (const float*)d_in[1];   // (32,4096,512)
    // d_in[2] = dustbin_token : unused by the reference computation
    const float* dparam  = (const float*)d_in[3];   // (1,)
    float* out = (float*)d_out;

    uot_fused<<<B_ * BLOCKS_PER_B, THREADS1>>>(prompt, vfeats, dparam, out);
}

// round 15
// speedup vs baseline: 1.3490x; 1.0351x over previous
#include <cuda_runtime.h>
#include <cuda_bf16.h>
#include <math.h>
#include <stdint.h>

// Problem constants
#define B_  32
#define N_  4096
#define C_  512
#define EPS_INV 10.0f          // 1/EPS_SINKHORN

#define THREADS1 256           // 8 warps
#define NWARPS (THREADS1 / 32)
#define BLOCKS_PER_B 18        // grid 576 = 18*32 (<= 592 resident slots, ONE wave)
#define WARPS_PER_B (BLOCKS_PER_B * NWARPS)   // 144 warps share one batch's 4096 rows

// Per-batch accumulators (allocation-free rule: __device__ globals; zero-init
// at module load, re-zeroed by the finishing block for graph replay)
__device__ float        g_vec[B_ * C_];     // 64KB: REDG-accumulated weighted sums
__device__ float        g_E[B_];            // REDG-accumulated exp-sums
__device__ unsigned int g_cnt[B_];          // last-arrival counters

// ---------------------------------------------------------------------------
// Fused single-pass kernel: R14's balanced warp-interleaved layout (+2.8%
// placement cap instead of +15.6%) COMBINED with R7's register snapshot
// prefetch (next row's LDG.128 issued before the current row's reduce/exp
// chain, lifting per-warp duty cycle ~76% -> ~84%). Prompt lives in smem,
// pre-normalized in place, so the prefetch double-buffer fits 64 regs.
//
// Per row: e = exp(10*(cos_sim - 1)) (shift m=0 valid since cos_sim <= 1),
// accumulate (e/|v|)*v and e. Softmax Z folds out analytically:
//   obs = num / (E + 1e-6*S),  total_mass = E / S,  S = E + exp(-10*dustbin).
// ---------------------------------------------------------------------------
__global__ __launch_bounds__(THREADS1, 4)
void uot_fused(const float* __restrict__ prompt,
               const float* __restrict__ vfeats,
               const float* __restrict__ dustbin_param,
               float* __restrict__ out)
{
    const int b    = blockIdx.x / BLOCKS_PER_B;
    const int jblk = blockIdx.x % BLOCKS_PER_B;
    const int tid  = threadIdx.x;
    const int wid  = tid >> 5;
    const int lane = tid & 31;
    const int wb   = jblk * NWARPS + wid;    // warp index within batch: 0..143

    __shared__ float sp[C_];                 // normalized prompt (2KB)
    __shared__ float sacc[NWARPS][C_];       // 16KB
    __shared__ float sEw[NWARPS];
    __shared__ float s_pinv;
    __shared__ int   sLast;

    // ---- Load prompt, compute norm, normalize IN SMEM ----
    float ss = 0.f;
    #pragma unroll
    for (int i = tid; i < C_; i += THREADS1) {
        float v = prompt[b * C_ + i];
        sp[i] = v;
        ss += v * v;
    }
    #pragma unroll
    for (int o = 16; o; o >>= 1) ss += __shfl_xor_sync(0xffffffffu, ss, o);
    if (lane == 0) sEw[wid] = ss;
    __syncthreads();
    if (tid == 0) {
        float t = 0.f;
        #pragma unroll
        for (int w = 0; w < NWARPS; w++) t += sEw[w];
        s_pinv = rsqrtf(fmaxf(t, 1e-24f));
    }
    __syncthreads();
    {
        const float pinv = s_pinv;
        #pragma unroll
        for (int i = tid; i < C_; i += THREADS1) sp[i] *= pinv;
    }
    __syncthreads();

    // ---- Main streaming loop: rows wb, wb+144, ... with snapshot prefetch ----
    float acc[16];
    #pragma unroll
    for (int i = 0; i < 16; i++) acc[i] = 0.f;
    float Eacc = 0.f;

    const float*  vb  = vfeats + (size_t)b * N_ * C_;
    const float4* pr4 = (const float4*)sp;

    float4 v[4];
    {   // prologue: first row prefetch
        const float4* row0 = (const float4*)(vb + (size_t)wb * C_);
        #pragma unroll
        for (int j = 0; j < 4; j++) v[j] = __ldcs(row0 + j * 32 + lane);
    }

    for (int r = wb; r < N_; r += WARPS_PER_B) {
        // Snapshot current row, immediately issue next row's loads
        float4 c[4];
        #pragma unroll
        for (int j = 0; j < 4; j++) c[j] = v[j];

        const int rn = r + WARPS_PER_B;
        if (rn < N_) {
            const float4* rown = (const float4*)(vb + (size_t)rn * C_);
            #pragma unroll
            for (int j = 0; j < 4; j++) v[j] = __ldcs(rown + j * 32 + lane);
        }

        // Reduce/exp chain on current row (overlaps next row's DRAM latency)
        float dpv = 0.f, dvv = 0.f;
        #pragma unroll
        for (int j = 0; j < 4; j++) {
            float4 p4 = pr4[j * 32 + lane];
            dpv += c[j].x * p4.x + c[j].y * p4.y + c[j].z * p4.z + c[j].w * p4.w;
            dvv += c[j].x * c[j].x + c[j].y * c[j].y + c[j].z * c[j].z + c[j].w * c[j].w;
        }
        #pragma unroll
        for (int o = 16; o; o >>= 1) {       // interleaved butterflies overlap
            dpv += __shfl_xor_sync(0xffffffffu, dpv, o);
            dvv += __shfl_xor_sync(0xffffffffu, dvv, o);
        }
        float invn = rsqrtf(fmaxf(dvv, 1e-24f));
        float e    = __expf(EPS_INV * (dpv * invn - 1.0f));   // sp already unit-norm
        float w    = e * invn;               // weight applied to the RAW row
        Eacc += e;
        #pragma unroll
        for (int j = 0; j < 4; j++) {
            acc[j * 4 + 0] += w * c[j].x;
            acc[j * 4 + 1] += w * c[j].y;
            acc[j * 4 + 2] += w * c[j].z;
            acc[j * 4 + 3] += w * c[j].w;
        }
    }

    // ---- Cross-warp combine in smem, then one REDG flush per block ----
    float4* sa4 = (float4*)sacc[wid];
    #pragma unroll
    for (int j = 0; j < 4; j++)
        sa4[j * 32 + lane] = make_float4(acc[j*4+0], acc[j*4+1], acc[j*4+2], acc[j*4+3]);
    __syncthreads();                         // also covers sEw reuse from prologue
    if (lane == 0) sEw[wid] = Eacc;
    __syncthreads();

    #pragma unroll
    for (int c = tid; c < C_; c += THREADS1) {   // 2 iterations
        float s = 0.f;
        #pragma unroll
        for (int w = 0; w < NWARPS; w++) s += sacc[w][c];
        atomicAdd(&g_vec[b * C_ + c], s);        // no return use -> REDG
    }
    if (tid == 0) {
        float s = 0.f;
        #pragma unroll
        for (int w = 0; w < NWARPS; w++) s += sEw[w];
        atomicAdd(&g_E[b], s);
    }

    // ---- Last-of-18 block per batch finalizes ----
    __threadfence();                         // release REDs
    __syncthreads();
    if (tid == 0) {
        unsigned int old = atomicAdd(&g_cnt[b], 1u);
        sLast = (old == BLOCKS_PER_B - 1);
    }
    __syncthreads();
    if (!sLast) return;
    __threadfence();                         // acquire others' REDs

    const float E    = g_E[b];               // no prior LDG of g_vec/g_E here: L1 clean
    const float ebin = __expf(-EPS_INV * dustbin_param[0]);
    const float S    = E + ebin;
    const float dinv = 1.0f / (E + 1e-6f * S);

    #pragma unroll
    for (int c = tid; c < C_; c += THREADS1) {
        float num = g_vec[b * C_ + c];
        out[b * C_ + c] = num * dinv;
        g_vec[b * C_ + c] = 0.f;             // re-arm for next graph replay
    }
    if (tid == 0) {
        out[B_ * C_ + b] = E / S;            // total_mass
        g_E[b] = 0.f;
        g_cnt[b] = 0u;
    }
}

// ---------------------------------------------------------------------------
extern "C" void kernel_launch(void* const* d_in, const int* in_sizes, int n_in,
                              void* d_out, int out_size)
{
    const float* prompt  = (const float*)d_in[0];   // (32,1,512)
    const float* vfeats  = (const float*)d_in[1];   // (32,4096,512)
    // d_in[2] = dustbin_token : unused by the reference computation
    const float* dparam  = (const float*)d_in[3];   // (1,)
    float* out = (float*)d_out;

    uot_fused<<<B_ * BLOCKS_PER_B, THREADS1>>>(prompt, vfeats, dparam, out);
}